// round 1
// baseline (speedup 1.0000x reference)
#include <cuda_runtime.h>

// MemoryTemporalBlock fused kernel (fp32 baseline).
// One CTA per (b, n) tile: T=12 tokens, D=256 features.
//   - x tile -> smem
//   - QKV projection: thread e computes column e of Q,K,V for all 12 t
//     (warp h == head h, lane == dk)
//   - causal temporal attention + memory-bank attention via warp shuffles
//   - sigmoid-gated fusion
//   - fc projection + residual + LayerNorm, all in the same CTA
// No intermediate global traffic: only x read + out written + L2-resident weights.

#define BB 8
#define NN 2048
#define TT 12
#define DD 256
#define HH 8
#define DKK 32
#define MMM 8

__device__ __forceinline__ float warp_sum(float v) {
#pragma unroll
    for (int o = 16; o; o >>= 1) v += __shfl_xor_sync(0xffffffffu, v, o);
    return v;
}

__global__ void __launch_bounds__(256, 2)
mtb_kernel(const float* __restrict__ x,
           const float* __restrict__ wq, const float* __restrict__ bq,
           const float* __restrict__ wk, const float* __restrict__ bk,
           const float* __restrict__ wv, const float* __restrict__ bv,
           const float* __restrict__ memk, const float* __restrict__ memv,
           const float* __restrict__ wf, const float* __restrict__ bf,
           const float* __restrict__ gamma, const float* __restrict__ beta,
           const float* __restrict__ alpha_p,
           float* __restrict__ out)
{
    __shared__ float xs[TT][DD];   // input tile (kept for residual)
    __shared__ float os[TT][DD];   // attention output / pre-LN buffer

    const int tile = blockIdx.x;          // b*N + n
    const float* xt = x + (size_t)tile * (TT * DD);
    const int tid = threadIdx.x;

    // ---- load x tile (coalesced float4) ----
    {
        const float4* src = (const float4*)xt;
        float4* dst = (float4*)&xs[0][0];
#pragma unroll
        for (int i = 0; i < 3; i++) dst[tid + 256 * i] = src[tid + 256 * i];
    }
    __syncthreads();

    const int e  = tid;
    const int h  = tid >> 5;
    const int dk = tid & 31;

    // ---- QKV projection: y[t,e] = sum_d x[t,d] * W[e,d] + b[e] ----
    float q[TT], k[TT], v[TT];
#pragma unroll
    for (int t = 0; t < TT; t++) { q[t] = 0.f; k[t] = 0.f; v[t] = 0.f; }

    const float4* wq4 = (const float4*)(wq + (size_t)e * DD);
    const float4* wk4 = (const float4*)(wk + (size_t)e * DD);
    const float4* wv4 = (const float4*)(wv + (size_t)e * DD);

#pragma unroll 2
    for (int d4 = 0; d4 < DD / 4; ++d4) {
        const float4 aq = __ldg(wq4 + d4);
        const float4 ak = __ldg(wk4 + d4);
        const float4 av = __ldg(wv4 + d4);
#pragma unroll
        for (int t = 0; t < TT; t++) {
            const float4 xv = *(const float4*)&xs[t][4 * d4];
            q[t] = fmaf(xv.x, aq.x, fmaf(xv.y, aq.y, fmaf(xv.z, aq.z, fmaf(xv.w, aq.w, q[t]))));
            k[t] = fmaf(xv.x, ak.x, fmaf(xv.y, ak.y, fmaf(xv.z, ak.z, fmaf(xv.w, ak.w, k[t]))));
            v[t] = fmaf(xv.x, av.x, fmaf(xv.y, av.y, fmaf(xv.z, av.z, fmaf(xv.w, av.w, v[t]))));
        }
    }
    {
        const float cbq = bq[e], cbk = bk[e], cbv = bv[e];
#pragma unroll
        for (int t = 0; t < TT; t++) { q[t] += cbq; k[t] += cbk; v[t] += cbv; }
    }

    // ---- memory bank (per head, per lane dk) ----
    float mk[MMM], mv[MMM];
#pragma unroll
    for (int m = 0; m < MMM; m++) {
        mk[m] = memk[(h * MMM + m) * DKK + dk];
        mv[m] = memv[(h * MMM + m) * DKK + dk];
    }

    const float scale = 0.17677669529663687f;   // 1/sqrt(32)
    const float alpha = alpha_p[0];
    const float wl = 1.f / (1.f + expf(-alpha));

    // ---- attention: warp == head, lane == dk ----
    float oc[TT];
#pragma unroll
    for (int t = 0; t < TT; t++) {
        // causal temporal attention over s <= t (masked entries contribute 0)
        float sc[TT];
        float mx = -1e30f;
#pragma unroll
        for (int s = 0; s < TT; s++) {
            if (s > t) break;
            const float p = warp_sum(q[t] * k[s]) * scale;
            sc[s] = p;
            mx = fmaxf(mx, p);
        }
        float den = 0.f, ot = 0.f;
#pragma unroll
        for (int s = 0; s < TT; s++) {
            if (s > t) break;
            const float w = expf(sc[s] - mx);
            den += w;
            ot = fmaf(w, v[s], ot);
        }
        ot /= den;

        // memory-bank attention over M slots
        float scm[MMM];
        float mxm = -1e30f;
#pragma unroll
        for (int m = 0; m < MMM; m++) {
            const float p = warp_sum(q[t] * mk[m]) * scale;
            scm[m] = p;
            mxm = fmaxf(mxm, p);
        }
        float dm = 0.f, ol = 0.f;
#pragma unroll
        for (int m = 0; m < MMM; m++) {
            const float w = expf(scm[m] - mxm);
            dm += w;
            ol = fmaf(w, mv[m], ol);
        }
        ol /= dm;

        oc[t] = ot * (1.f - wl) + ol * wl;
    }

    // ---- stage attention output for fc ----
#pragma unroll
    for (int t = 0; t < TT; t++) os[t][e] = oc[t];
    __syncthreads();

    // ---- fc projection: y[t,e] = sum_f os[t,f] * wf[e,f] + bf[e] + x[t,e] ----
    float y[TT];
#pragma unroll
    for (int t = 0; t < TT; t++) y[t] = 0.f;

    const float4* wf4 = (const float4*)(wf + (size_t)e * DD);
#pragma unroll 2
    for (int d4 = 0; d4 < DD / 4; ++d4) {
        const float4 af = __ldg(wf4 + d4);
#pragma unroll
        for (int t = 0; t < TT; t++) {
            const float4 xv = *(const float4*)&os[t][4 * d4];
            y[t] = fmaf(xv.x, af.x, fmaf(xv.y, af.y, fmaf(xv.z, af.z, fmaf(xv.w, af.w, y[t]))));
        }
    }
    {
        const float cbf = bf[e];
#pragma unroll
        for (int t = 0; t < TT; t++) y[t] += cbf + xs[t][e];
    }

    __syncthreads();   // all reads of os done
#pragma unroll
    for (int t = 0; t < TT; t++) os[t][e] = y[t];
    __syncthreads();

    // ---- LayerNorm over D per row t (warp per row) ----
    const int lane = tid & 31;
    const int wrp = tid >> 5;
    for (int t = wrp; t < TT; t += 8) {
        float s = 0.f, s2 = 0.f;
#pragma unroll
        for (int j = 0; j < 8; j++) {
            const float val = os[t][lane + 32 * j];
            s += val;
            s2 = fmaf(val, val, s2);
        }
        s = warp_sum(s);
        s2 = warp_sum(s2);
        const float mu = s * (1.f / 256.f);
        const float var = s2 * (1.f / 256.f) - mu * mu;
        const float inv = rsqrtf(var + 1e-5f);
        float* orow = out + (size_t)tile * (TT * DD) + t * DD;
#pragma unroll
        for (int j = 0; j < 8; j++) {
            const int c = lane + 32 * j;
            orow[c] = (os[t][c] - mu) * inv * gamma[c] + beta[c];
        }
    }
}

extern "C" void kernel_launch(void* const* d_in, const int* in_sizes, int n_in,
                              void* d_out, int out_size)
{
    (void)in_sizes; (void)n_in; (void)out_size;
    const float* x     = (const float*)d_in[0];
    const float* Wq_w  = (const float*)d_in[1];
    const float* Wq_b  = (const float*)d_in[2];
    const float* Wk_w  = (const float*)d_in[3];
    const float* Wk_b  = (const float*)d_in[4];
    const float* Wv_w  = (const float*)d_in[5];
    const float* Wv_b  = (const float*)d_in[6];
    const float* mem_k = (const float*)d_in[7];
    const float* mem_v = (const float*)d_in[8];
    const float* fc_w  = (const float*)d_in[9];
    const float* fc_b  = (const float*)d_in[10];
    const float* gamma = (const float*)d_in[11];
    const float* beta  = (const float*)d_in[12];
    const float* alpha = (const float*)d_in[13];
    float* out = (float*)d_out;

    mtb_kernel<<<BB * NN, 256>>>(x, Wq_w, Wq_b, Wk_w, Wk_b, Wv_w, Wv_b,
                                 mem_k, mem_v, fc_w, fc_b, gamma, beta, alpha, out);
}

// round 2
// speedup vs baseline: 2.1549x; 2.1549x over previous
#include <cuda_runtime.h>

// MemoryTemporalBlock — fused, fp32x2 (packed FFMA2) version.
// Kernel 1 (prep): transpose 4 weight matrices into Wt[mat][dpair][e] (float2 over d)
//                  so the main kernel's weight loads are lane-coalesced.
// Kernel 2 (main): one CTA per (b,n) tile, 128 threads, each thread owns
//                  feature columns e and e+128. x is staged transposed in smem
//                  (xst[d][t]) so the 12 t-accumulators run as 6 f32x2 pairs.

#define TT 12
#define DD 256
#define HH 8
#define MMM 8

typedef unsigned long long ull;

__device__ float2 g_Wt[4][128][256];   // [mat][d/2][e] = (W[e][2dp], W[e][2dp+1])

static __device__ __forceinline__ ull pack2(float v) {
    ull r;
    asm("mov.b64 %0, {%1, %2};" : "=l"(r)
        : "r"(__float_as_uint(v)), "r"(__float_as_uint(v)));
    return r;
}
static __device__ __forceinline__ void fma2(ull &acc, ull a, ull b) {
    asm("fma.rn.f32x2 %0, %1, %2, %0;" : "+l"(acc) : "l"(a), "l"(b));
}
static __device__ __forceinline__ float2 unpk(ull v) {
    unsigned int lo, hi;
    asm("mov.b64 {%0, %1}, %2;" : "=r"(lo), "=r"(hi) : "l"(v));
    return make_float2(__uint_as_float(lo), __uint_as_float(hi));
}
static __device__ __forceinline__ float warp_sum(float v) {
#pragma unroll
    for (int o = 16; o; o >>= 1) v += __shfl_xor_sync(0xffffffffu, v, o);
    return v;
}

// acc[0..5] (t-pairs) += x(t-pairs at this d) * w  for two consecutive d
#define ACC6(A, X0, X1, X2, W) do { ull _w = pack2(W); \
    fma2(A[0], X0.x, _w); fma2(A[1], X0.y, _w); fma2(A[2], X1.x, _w); \
    fma2(A[3], X1.y, _w); fma2(A[4], X2.x, _w); fma2(A[5], X2.y, _w); } while (0)

__global__ void prep_kernel(const float* __restrict__ wq, const float* __restrict__ wk,
                            const float* __restrict__ wv, const float* __restrict__ wf)
{
    int i = blockIdx.x * blockDim.x + threadIdx.x;   // 4*128*256 total
    int e   = i & 255;
    int dp  = (i >> 8) & 127;
    int mat = i >> 15;
    const float* W = (mat == 0) ? wq : (mat == 1) ? wk : (mat == 2) ? wv : wf;
    float2 v = make_float2(__ldg(W + e * DD + 2 * dp), __ldg(W + e * DD + 2 * dp + 1));
    g_Wt[mat][dp][e] = v;
}

__global__ void __launch_bounds__(128, 3)
mtb_kernel(const float* __restrict__ x,
           const float* __restrict__ bq, const float* __restrict__ bk,
           const float* __restrict__ bv,
           const float* __restrict__ memk, const float* __restrict__ memv,
           const float* __restrict__ bf,
           const float* __restrict__ gamma, const float* __restrict__ beta,
           const float* __restrict__ alpha_p,
           float* __restrict__ out)
{
    __shared__ __align__(16) float xst[DD * TT];   // x transposed: [d][t]; later reused as osn[t][e]
    __shared__ __align__(16) float obuf[DD * TT];  // stage x [t][e]; later ost[e][t]

    const int tile = blockIdx.x;
    const int tid  = threadIdx.x;
    const int lane = tid & 31;
    const int e0 = tid, e1 = tid + 128;

    // ---- stage x (coalesced), then transpose into xst[d][t] ----
    {
        const float4* xg = (const float4*)(x + (size_t)tile * (TT * DD));
        float4* sg = (float4*)obuf;
#pragma unroll
        for (int p = 0; p < 6; p++) sg[p * 128 + tid] = xg[p * 128 + tid];
    }
    __syncthreads();
#pragma unroll
    for (int dd = 0; dd < 2; dd++) {
        const int d = tid + 128 * dd;
#pragma unroll
        for (int t = 0; t < TT; t++) xst[d * TT + t] = obuf[t * DD + d];
    }
    __syncthreads();

    // ---- QKV projection with packed f32x2 FMAs ----
    ull aq[2][6], ak[2][6], av[2][6];
#pragma unroll
    for (int g = 0; g < 2; g++)
#pragma unroll
        for (int j = 0; j < 6; j++) { aq[g][j] = 0ull; ak[g][j] = 0ull; av[g][j] = 0ull; }

#pragma unroll 2
    for (int dp = 0; dp < 128; dp++) {
        const float2 wq0 = g_Wt[0][dp][e0];
        const float2 wq1 = g_Wt[0][dp][e1];
        const float2 wk0 = g_Wt[1][dp][e0];
        const float2 wk1 = g_Wt[1][dp][e1];
        const float2 wv0 = g_Wt[2][dp][e0];
        const float2 wv1 = g_Wt[2][dp][e1];
        const ulonglong2* xr0 = (const ulonglong2*)(xst + (2 * dp) * TT);
        const ulonglong2* xr1 = (const ulonglong2*)(xst + (2 * dp + 1) * TT);
        const ulonglong2 xa = xr0[0], xb = xr0[1], xc = xr0[2];
        const ulonglong2 xd = xr1[0], xe = xr1[1], xf = xr1[2];

        ACC6(aq[0], xa, xb, xc, wq0.x); ACC6(aq[0], xd, xe, xf, wq0.y);
        ACC6(aq[1], xa, xb, xc, wq1.x); ACC6(aq[1], xd, xe, xf, wq1.y);
        ACC6(ak[0], xa, xb, xc, wk0.x); ACC6(ak[0], xd, xe, xf, wk0.y);
        ACC6(ak[1], xa, xb, xc, wk1.x); ACC6(ak[1], xd, xe, xf, wk1.y);
        ACC6(av[0], xa, xb, xc, wv0.x); ACC6(av[0], xd, xe, xf, wv0.y);
        ACC6(av[1], xa, xb, xc, wv1.x); ACC6(av[1], xd, xe, xf, wv1.y);
    }

    // ---- unpack + biases ----
    float qf[2][TT], kf[2][TT], vf[2][TT];
#pragma unroll
    for (int g = 0; g < 2; g++) {
        const int e = (g == 0) ? e0 : e1;
        const float cq = __ldg(bq + e), ck = __ldg(bk + e), cv = __ldg(bv + e);
#pragma unroll
        for (int j = 0; j < 6; j++) {
            float2 u;
            u = unpk(aq[g][j]); qf[g][2 * j] = u.x + cq; qf[g][2 * j + 1] = u.y + cq;
            u = unpk(ak[g][j]); kf[g][2 * j] = u.x + ck; kf[g][2 * j + 1] = u.y + ck;
            u = unpk(av[g][j]); vf[g][2 * j] = u.x + cv; vf[g][2 * j + 1] = u.y + cv;
        }
    }

    // ---- attention (warp == head within each half, lane == dk) ----
    const float scale = 0.17677669529663687f;   // 1/sqrt(32)
    const float wl = 1.f / (1.f + __expf(-__ldg(alpha_p)));
    const float wt = 1.f - wl;

#pragma unroll
    for (int g = 0; g < 2; g++) {
        const int h = (tid >> 5) + 4 * g;
        float mk[MMM], mv[MMM];
#pragma unroll
        for (int m = 0; m < MMM; m++) {
            mk[m] = __ldg(memk + (h * MMM + m) * 32 + lane);
            mv[m] = __ldg(memv + (h * MMM + m) * 32 + lane);
        }
        const int e = (g == 0) ? e0 : e1;
#pragma unroll
        for (int t = 0; t < TT; t++) {
            float den = 0.f, ot = 0.f;
#pragma unroll
            for (int s = 0; s < TT; s++) {
                if (s > t) break;
                const float p = warp_sum(qf[g][t] * kf[g][s]) * scale;
                const float w = __expf(p);       // scores are O(1); no max-sub needed
                den += w; ot = fmaf(w, vf[g][s], ot);
            }
            float dm = 0.f, ol = 0.f;
#pragma unroll
            for (int m = 0; m < MMM; m++) {
                const float p = warp_sum(qf[g][t] * mk[m]) * scale;
                const float w = __expf(p);
                dm += w; ol = fmaf(w, mv[m], ol);
            }
            obuf[e * TT + t] = (ot / den) * wt + (ol / dm) * wl;  // ost[e][t]
        }
    }
    __syncthreads();

    // ---- fc projection (packed f32x2) ----
    ull ao[2][6];
#pragma unroll
    for (int g = 0; g < 2; g++)
#pragma unroll
        for (int j = 0; j < 6; j++) ao[g][j] = 0ull;

#pragma unroll 2
    for (int dp = 0; dp < 128; dp++) {
        const float2 wf0 = g_Wt[3][dp][e0];
        const float2 wf1 = g_Wt[3][dp][e1];
        const ulonglong2* or0 = (const ulonglong2*)(obuf + (2 * dp) * TT);
        const ulonglong2* or1 = (const ulonglong2*)(obuf + (2 * dp + 1) * TT);
        const ulonglong2 oa = or0[0], ob = or0[1], oc = or0[2];
        const ulonglong2 od = or1[0], oe = or1[1], of = or1[2];
        ACC6(ao[0], oa, ob, oc, wf0.x); ACC6(ao[0], od, oe, of, wf0.y);
        ACC6(ao[1], oa, ob, oc, wf1.x); ACC6(ao[1], od, oe, of, wf1.y);
    }

    // ---- bias + residual ----
    float y[2][TT];
#pragma unroll
    for (int g = 0; g < 2; g++) {
        const int e = (g == 0) ? e0 : e1;
        const float cb = __ldg(bf + e);
#pragma unroll
        for (int j = 0; j < 6; j++) {
            const float2 u = unpk(ao[g][j]);
            y[g][2 * j]     = u.x + cb + xst[e * TT + 2 * j];
            y[g][2 * j + 1] = u.y + cb + xst[e * TT + 2 * j + 1];
        }
    }
    __syncthreads();                 // all xst reads done before overwrite

    float* osn = xst;                // reuse as [t][e]
#pragma unroll
    for (int t = 0; t < TT; t++) { osn[t * DD + e0] = y[0][t]; osn[t * DD + e1] = y[1][t]; }
    __syncthreads();

    // ---- LayerNorm (warp per row) ----
    const int wrp = tid >> 5;
    for (int t = wrp; t < TT; t += 4) {
        const float* row = osn + t * DD;
        float s = 0.f, s2 = 0.f;
#pragma unroll
        for (int j = 0; j < 8; j++) {
            const float val = row[lane + 32 * j];
            s += val; s2 = fmaf(val, val, s2);
        }
        s = warp_sum(s); s2 = warp_sum(s2);
        const float mu = s * (1.f / 256.f);
        const float var = s2 * (1.f / 256.f) - mu * mu;
        const float inv = rsqrtf(var + 1e-5f);
        float* orow = out + (size_t)tile * (TT * DD) + t * DD;
#pragma unroll
        for (int j = 0; j < 8; j++) {
            const int c = lane + 32 * j;
            orow[c] = (row[c] - mu) * inv * __ldg(gamma + c) + __ldg(beta + c);
        }
    }
}

extern "C" void kernel_launch(void* const* d_in, const int* in_sizes, int n_in,
                              void* d_out, int out_size)
{
    (void)in_sizes; (void)n_in; (void)out_size;
    const float* x     = (const float*)d_in[0];
    const float* Wq_w  = (const float*)d_in[1];
    const float* Wq_b  = (const float*)d_in[2];
    const float* Wk_w  = (const float*)d_in[3];
    const float* Wk_b  = (const float*)d_in[4];
    const float* Wv_w  = (const float*)d_in[5];
    const float* Wv_b  = (const float*)d_in[6];
    const float* mem_k = (const float*)d_in[7];
    const float* mem_v = (const float*)d_in[8];
    const float* fc_w  = (const float*)d_in[9];
    const float* fc_b  = (const float*)d_in[10];
    const float* gamma = (const float*)d_in[11];
    const float* beta  = (const float*)d_in[12];
    const float* alpha = (const float*)d_in[13];
    float* out = (float*)d_out;

    prep_kernel<<<512, 256>>>(Wq_w, Wk_w, Wv_w, fc_w);
    mtb_kernel<<<16384, 128>>>(x, Wq_b, Wk_b, Wv_b, mem_k, mem_v,
                               fc_b, gamma, beta, alpha, out);
}

// round 3
// speedup vs baseline: 2.9464x; 1.3673x over previous
#include <cuda_runtime.h>
#include <cstdint>

// MemoryTemporalBlock — tf32 tensor-core version.
// prep_kernel: repack 4 weight matrices into tf32 "fragment order" so the main
//              kernel's B-operand loads are coalesced LDG.64.
// mtb_kernel:  one CTA per 4 (b,n) tiles (M=48 rows). QKV via mma.sync tf32,
//              attention + gating in fp32 from smem, fc GEMM + residual + LN.

#define TT 12
#define DD 256
#define GG 4            // (b,n) tiles per CTA
#define MROWS (GG * TT) // 48
#define LDP 260         // padded smem row stride (floats): bank = 4r + c
#define MMM 8

// Wfrag[mat][wn(8)][kstep(32)][ntile(4)][lane(32)] as float2 (tf32 bits)
__device__ float2 g_Wfrag[4][8][32][4][32];

static __device__ __forceinline__ uint32_t f2tf32(float f) {
    uint32_t r; asm("cvt.rna.tf32.f32 %0, %1;" : "=r"(r) : "f"(f)); return r;
}
static __device__ __forceinline__ void mma_tf32(float* c, const uint32_t* a,
                                                uint32_t b0, uint32_t b1) {
    asm("mma.sync.aligned.m16n8k8.row.col.f32.tf32.tf32.f32 "
        "{%0,%1,%2,%3}, {%4,%5,%6,%7}, {%8,%9}, {%0,%1,%2,%3};"
        : "+f"(c[0]), "+f"(c[1]), "+f"(c[2]), "+f"(c[3])
        : "r"(a[0]), "r"(a[1]), "r"(a[2]), "r"(a[3]), "r"(b0), "r"(b1));
}
static __device__ __forceinline__ float warp_sum(float v) {
#pragma unroll
    for (int o = 16; o; o >>= 1) v += __shfl_xor_sync(0xffffffffu, v, o);
    return v;
}

__global__ void prep_kernel(const float* __restrict__ wq, const float* __restrict__ wk,
                            const float* __restrict__ wv, const float* __restrict__ wf)
{
    // one thread per float2 slot: 4*8*32*4*32 = 131072
    int i = blockIdx.x * blockDim.x + threadIdx.x;
    int lane = i & 31;
    int nt   = (i >> 5) & 3;
    int kk   = (i >> 7) & 31;
    int wn   = (i >> 12) & 7;
    int mat  = i >> 15;
    const float* W = (mat == 0) ? wq : (mat == 1) ? wk : (mat == 2) ? wv : wf;
    int e = wn * 32 + nt * 8 + (lane >> 2);
    int d = kk * 8 + (lane & 3);
    float2 v;
    v.x = __uint_as_float(f2tf32(__ldg(W + e * DD + d)));
    v.y = __uint_as_float(f2tf32(__ldg(W + e * DD + d + 4)));
    g_Wfrag[mat][wn][kk][nt][lane] = v;
}

__global__ void __launch_bounds__(256, 1)
mtb_kernel(const float* __restrict__ x,
           const float* __restrict__ bq, const float* __restrict__ bk,
           const float* __restrict__ bv,
           const float* __restrict__ memk, const float* __restrict__ memv,
           const float* __restrict__ bf,
           const float* __restrict__ gamma, const float* __restrict__ beta,
           const float* __restrict__ alpha_p,
           float* __restrict__ out)
{
    extern __shared__ float sm[];
    float* xs = sm;                  // [MROWS][LDP] input (A operand + residual)
    float* qs = sm + 1 * MROWS * LDP;
    float* ks = sm + 2 * MROWS * LDP;
    float* vs = sm + 3 * MROWS * LDP;

    const int tid  = threadIdx.x;
    const int w    = tid >> 5;
    const int lane = tid & 31;
    const size_t gbase = (size_t)blockIdx.x * (MROWS * DD);

    // ---- load x tile (coalesced float4 into padded rows) ----
    {
        const float4* xg = (const float4*)(x + gbase);
#pragma unroll
        for (int p = 0; p < 12; p++) {
            const int idx = p * 256 + tid;        // float4 index
            const int r = idx >> 6, cg = idx & 63;
            *(float4*)(xs + r * LDP + cg * 4) = xg[idx];
        }
    }
    __syncthreads();

    // ---- QKV GEMM: tf32 mma, one K sweep, 3 accumulator chains ----
    float acc[3][3][4][4];   // [mat][mtile][ntile][reg]
#pragma unroll
    for (int m = 0; m < 3; m++)
#pragma unroll
        for (int mt = 0; mt < 3; mt++)
#pragma unroll
            for (int nt = 0; nt < 4; nt++)
#pragma unroll
                for (int j = 0; j < 4; j++) acc[m][mt][nt][j] = 0.f;

    const float2* __restrict__ B0 = &g_Wfrag[0][w][0][0][0];
    const float2* __restrict__ B1 = &g_Wfrag[1][w][0][0][0];
    const float2* __restrict__ B2 = &g_Wfrag[2][w][0][0][0];

#pragma unroll 4
    for (int kk = 0; kk < 32; kk++) {
        uint32_t a[3][4];
#pragma unroll
        for (int mt = 0; mt < 3; mt++) {
            const int r = mt * 16 + (lane >> 2);
            const int c = kk * 8 + (lane & 3);
            a[mt][0] = f2tf32(xs[r * LDP + c]);
            a[mt][1] = f2tf32(xs[(r + 8) * LDP + c]);
            a[mt][2] = f2tf32(xs[r * LDP + c + 4]);
            a[mt][3] = f2tf32(xs[(r + 8) * LDP + c + 4]);
        }
#pragma unroll
        for (int nt = 0; nt < 4; nt++) {
            const int off = (kk * 4 + nt) * 32 + lane;
            const float2 bqf = __ldg(B0 + off);
            const float2 bkf = __ldg(B1 + off);
            const float2 bvf = __ldg(B2 + off);
#pragma unroll
            for (int mt = 0; mt < 3; mt++) {
                mma_tf32(acc[0][mt][nt], a[mt], __float_as_uint(bqf.x), __float_as_uint(bqf.y));
                mma_tf32(acc[1][mt][nt], a[mt], __float_as_uint(bkf.x), __float_as_uint(bkf.y));
                mma_tf32(acc[2][mt][nt], a[mt], __float_as_uint(bvf.x), __float_as_uint(bvf.y));
            }
        }
    }

    // ---- store Q,K,V (+bias) to smem ----
#pragma unroll
    for (int nt = 0; nt < 4; nt++) {
        const int col = w * 32 + nt * 8 + 2 * (lane & 3);
        const float2 cbq = __ldg((const float2*)(bq + col));
        const float2 cbk = __ldg((const float2*)(bk + col));
        const float2 cbv = __ldg((const float2*)(bv + col));
#pragma unroll
        for (int mt = 0; mt < 3; mt++) {
            const int r0 = mt * 16 + (lane >> 2);
#pragma unroll
            for (int h = 0; h < 2; h++) {     // row, row+8
                const int r = r0 + 8 * h;
                float2 vq = make_float2(acc[0][mt][nt][2 * h] + cbq.x, acc[0][mt][nt][2 * h + 1] + cbq.y);
                float2 vk = make_float2(acc[1][mt][nt][2 * h] + cbk.x, acc[1][mt][nt][2 * h + 1] + cbk.y);
                float2 vv = make_float2(acc[2][mt][nt][2 * h] + cbv.x, acc[2][mt][nt][2 * h + 1] + cbv.y);
                *(float2*)(qs + r * LDP + col) = vq;
                *(float2*)(ks + r * LDP + col) = vk;
                *(float2*)(vs + r * LDP + col) = vv;
            }
        }
    }
    __syncthreads();

    // ---- attention: 32 units (tile,head); warp w does units w*4..w*4+3 ----
    const float scale = 0.17677669529663687f;   // 1/sqrt(32)
    const float wl = 1.f / (1.f + __expf(-__ldg(alpha_p)));
    const float wt = 1.f - wl;

    float oc[GG][TT];                 // gated outputs, written after barrier
#pragma unroll
    for (int u = 0; u < 4; u++) {
        const int unit = w * 4 + u;
        const int tau = unit >> 3, h = unit & 7;
        const int rb = tau * TT;
        const int cb = h * 32 + lane;
        float qv[TT], kv[TT], vv[TT];
#pragma unroll
        for (int t = 0; t < TT; t++) {
            qv[t] = qs[(rb + t) * LDP + cb];
            kv[t] = ks[(rb + t) * LDP + cb];
            vv[t] = vs[(rb + t) * LDP + cb];
        }
        float mk[MMM], mv[MMM];
#pragma unroll
        for (int m = 0; m < MMM; m++) {
            mk[m] = __ldg(memk + (h * MMM + m) * 32 + lane);
            mv[m] = __ldg(memv + (h * MMM + m) * 32 + lane);
        }
#pragma unroll
        for (int t = 0; t < TT; t++) {
            float den = 0.f, ot = 0.f;
#pragma unroll
            for (int s = 0; s < TT; s++) {
                if (s > t) break;
                const float p = warp_sum(qv[t] * kv[s]) * scale;
                const float wgt = __expf(p);
                den += wgt; ot = fmaf(wgt, vv[s], ot);
            }
            float dm = 0.f, ol = 0.f;
#pragma unroll
            for (int m = 0; m < MMM; m++) {
                const float p = warp_sum(qv[t] * mk[m]) * scale;
                const float wgt = __expf(p);
                dm += wgt; ol = fmaf(wgt, mv[m], ol);
            }
            oc[u][t] = (ot / den) * wt + (ol / dm) * wl;
        }
    }
    __syncthreads();                  // all qs/ks/vs reads done
#pragma unroll
    for (int u = 0; u < 4; u++) {
        const int unit = w * 4 + u;
        const int rb = (unit >> 3) * TT;
        const int cb = (unit & 7) * 32 + lane;
#pragma unroll
        for (int t = 0; t < TT; t++) qs[(rb + t) * LDP + cb] = oc[u][t];
    }
    __syncthreads();

    // ---- fc GEMM (A = attention out in qs) ----
    float fa[3][4][4];
#pragma unroll
    for (int mt = 0; mt < 3; mt++)
#pragma unroll
        for (int nt = 0; nt < 4; nt++)
#pragma unroll
            for (int j = 0; j < 4; j++) fa[mt][nt][j] = 0.f;

    const float2* __restrict__ B3 = &g_Wfrag[3][w][0][0][0];
#pragma unroll 4
    for (int kk = 0; kk < 32; kk++) {
        uint32_t a[3][4];
#pragma unroll
        for (int mt = 0; mt < 3; mt++) {
            const int r = mt * 16 + (lane >> 2);
            const int c = kk * 8 + (lane & 3);
            a[mt][0] = f2tf32(qs[r * LDP + c]);
            a[mt][1] = f2tf32(qs[(r + 8) * LDP + c]);
            a[mt][2] = f2tf32(qs[r * LDP + c + 4]);
            a[mt][3] = f2tf32(qs[(r + 8) * LDP + c + 4]);
        }
#pragma unroll
        for (int nt = 0; nt < 4; nt++) {
            const float2 bff = __ldg(B3 + (kk * 4 + nt) * 32 + lane);
#pragma unroll
            for (int mt = 0; mt < 3; mt++)
                mma_tf32(fa[mt][nt], a[mt], __float_as_uint(bff.x), __float_as_uint(bff.y));
        }
    }

    // ---- bias + residual -> vs (pre-LN buffer) ----
#pragma unroll
    for (int nt = 0; nt < 4; nt++) {
        const int col = w * 32 + nt * 8 + 2 * (lane & 3);
        const float2 cbf = __ldg((const float2*)(bf + col));
#pragma unroll
        for (int mt = 0; mt < 3; mt++) {
            const int r0 = mt * 16 + (lane >> 2);
#pragma unroll
            for (int h = 0; h < 2; h++) {
                const int r = r0 + 8 * h;
                float2 res = *(const float2*)(xs + r * LDP + col);
                float2 y = make_float2(fa[mt][nt][2 * h] + cbf.x + res.x,
                                       fa[mt][nt][2 * h + 1] + cbf.y + res.y);
                *(float2*)(vs + r * LDP + col) = y;
            }
        }
    }
    __syncthreads();

    // ---- LayerNorm: warp per row (6 rows each) ----
    for (int r = w * 6; r < w * 6 + 6; r++) {
        const float* row = vs + r * LDP;
        float s = 0.f, s2 = 0.f;
#pragma unroll
        for (int j = 0; j < 8; j++) {
            const float val = row[lane + 32 * j];
            s += val; s2 = fmaf(val, val, s2);
        }
        s = warp_sum(s); s2 = warp_sum(s2);
        const float mu = s * (1.f / 256.f);
        const float var = s2 * (1.f / 256.f) - mu * mu;
        const float inv = rsqrtf(var + 1e-5f);
        float* orow = out + gbase + (size_t)r * DD;
#pragma unroll
        for (int j = 0; j < 8; j++) {
            const int c = lane + 32 * j;
            orow[c] = (row[c] - mu) * inv * __ldg(gamma + c) + __ldg(beta + c);
        }
    }
}

extern "C" void kernel_launch(void* const* d_in, const int* in_sizes, int n_in,
                              void* d_out, int out_size)
{
    (void)in_sizes; (void)n_in; (void)out_size;
    const float* x     = (const float*)d_in[0];
    const float* Wq_w  = (const float*)d_in[1];
    const float* Wq_b  = (const float*)d_in[2];
    const float* Wk_w  = (const float*)d_in[3];
    const float* Wk_b  = (const float*)d_in[4];
    const float* Wv_w  = (const float*)d_in[5];
    const float* Wv_b  = (const float*)d_in[6];
    const float* mem_k = (const float*)d_in[7];
    const float* mem_v = (const float*)d_in[8];
    const float* fc_w  = (const float*)d_in[9];
    const float* fc_b  = (const float*)d_in[10];
    const float* gamma = (const float*)d_in[11];
    const float* beta  = (const float*)d_in[12];
    const float* alpha = (const float*)d_in[13];
    float* out = (float*)d_out;

    const int smemBytes = 4 * MROWS * LDP * sizeof(float);   // 199680
    cudaFuncSetAttribute(mtb_kernel, cudaFuncAttributeMaxDynamicSharedMemorySize, smemBytes);

    prep_kernel<<<512, 256>>>(Wq_w, Wk_w, Wv_w, fc_w);
    mtb_kernel<<<16384 / GG, 256, smemBytes>>>(x, Wq_b, Wk_b, Wv_b, mem_k, mem_v,
                                               fc_b, gamma, beta, alpha, out);
}

// round 4
// speedup vs baseline: 4.6542x; 1.5796x over previous
#include <cuda_runtime.h>
#include <cstdint>

// MemoryTemporalBlock — tf32 tensor-core, spill-free, cheap-attention version.
// One CTA per 4 (b,n) tiles (M=48 rows), 256 threads, ~200KB smem, 1 CTA/SM.
// Sweeps: [Q+K fused] -> [V] -> attention -> [fc]; B operands prefetched from
// L2 in tf32 fragment order (prep kernel). A operands pre-converted to tf32.

#define TT 12
#define DD 256
#define GG 4
#define MROWS (GG * TT)
#define LDP 260
#define MMM 8
#define LOG2E 1.4426950408889634f

// Wfrag[mat][wn(8)][kstep(32)][ntile(4)][lane(32)] as float2 (tf32 bits)
__device__ float2 g_Wfrag[4][8][32][4][32];

static __device__ __forceinline__ uint32_t f2tf32(float f) {
    uint32_t r; asm("cvt.rna.tf32.f32 %0, %1;" : "=r"(r) : "f"(f)); return r;
}
static __device__ __forceinline__ float ex2(float x) {
    float r; asm("ex2.approx.f32 %0, %1;" : "=f"(r) : "f"(x)); return r;
}
static __device__ __forceinline__ void mma_tf32(float* c, const uint32_t* a,
                                                uint32_t b0, uint32_t b1) {
    asm("mma.sync.aligned.m16n8k8.row.col.f32.tf32.tf32.f32 "
        "{%0,%1,%2,%3}, {%4,%5,%6,%7}, {%8,%9}, {%0,%1,%2,%3};"
        : "+f"(c[0]), "+f"(c[1]), "+f"(c[2]), "+f"(c[3])
        : "r"(a[0]), "r"(a[1]), "r"(a[2]), "r"(a[3]), "r"(b0), "r"(b1));
}
static __device__ __forceinline__ float warp_sum(float v) {
#pragma unroll
    for (int o = 16; o; o >>= 1) v += __shfl_xor_sync(0xffffffffu, v, o);
    return v;
}
static __device__ __forceinline__ float gsum8(float v, unsigned m) {
    v += __shfl_xor_sync(m, v, 1);
    v += __shfl_xor_sync(m, v, 2);
    v += __shfl_xor_sync(m, v, 4);
    return v;
}

__global__ void prep_kernel(const float* __restrict__ wq, const float* __restrict__ wk,
                            const float* __restrict__ wv, const float* __restrict__ wf)
{
    int i = blockIdx.x * blockDim.x + threadIdx.x;
    int lane = i & 31;
    int nt   = (i >> 5) & 3;
    int kk   = (i >> 7) & 31;
    int wn   = (i >> 12) & 7;
    int mat  = i >> 15;
    const float* W = (mat == 0) ? wq : (mat == 1) ? wk : (mat == 2) ? wv : wf;
    int e = wn * 32 + nt * 8 + (lane >> 2);
    int d = kk * 8 + (lane & 3);
    float2 v;
    v.x = __uint_as_float(f2tf32(__ldg(W + e * DD + d)));
    v.y = __uint_as_float(f2tf32(__ldg(W + e * DD + d + 4)));
    g_Wfrag[mat][wn][kk][nt][lane] = v;
}

// GEMM sweep over K=256 for NM weight matrices; A = tf32 bits in smem [48][LDP].
template<int NM>
static __device__ __forceinline__ void gemm_sweep(
    const float* __restrict__ As, int lane,
    const float2* const* __restrict__ Bp,
    float acc[NM][3][4][4])
{
#pragma unroll
    for (int m = 0; m < NM; m++)
#pragma unroll
        for (int mt = 0; mt < 3; mt++)
#pragma unroll
            for (int nt = 0; nt < 4; nt++)
#pragma unroll
                for (int j = 0; j < 4; j++) acc[m][mt][nt][j] = 0.f;

    float2 b0[NM][4], b1[NM][4];
#pragma unroll
    for (int m = 0; m < NM; m++)
#pragma unroll
        for (int nt = 0; nt < 4; nt++) {
            b0[m][nt] = __ldg(Bp[m] + nt * 32 + lane);
            b1[m][nt] = __ldg(Bp[m] + (4 + nt) * 32 + lane);
        }

    const int r0 = lane >> 2, c0 = lane & 3;
#pragma unroll 2
    for (int kk = 0; kk < 32; kk++) {
        uint32_t a[3][4];
#pragma unroll
        for (int mt = 0; mt < 3; mt++) {
            const float* p = As + (mt * 16 + r0) * LDP + kk * 8 + c0;
            a[mt][0] = __float_as_uint(p[0]);
            a[mt][1] = __float_as_uint(p[8 * LDP]);
            a[mt][2] = __float_as_uint(p[4]);
            a[mt][3] = __float_as_uint(p[8 * LDP + 4]);
        }
        float2 bc[NM][4];
#pragma unroll
        for (int m = 0; m < NM; m++)
#pragma unroll
            for (int nt = 0; nt < 4; nt++) { bc[m][nt] = b0[m][nt]; b0[m][nt] = b1[m][nt]; }
        if (kk < 30) {
#pragma unroll
            for (int m = 0; m < NM; m++)
#pragma unroll
                for (int nt = 0; nt < 4; nt++)
                    b1[m][nt] = __ldg(Bp[m] + ((kk + 2) * 4 + nt) * 32 + lane);
        }
#pragma unroll
        for (int m = 0; m < NM; m++)
#pragma unroll
            for (int nt = 0; nt < 4; nt++)
#pragma unroll
                for (int mt = 0; mt < 3; mt++)
                    mma_tf32(acc[m][mt][nt], a[mt],
                             __float_as_uint(bc[m][nt].x), __float_as_uint(bc[m][nt].y));
    }
}

static __device__ __forceinline__ void store_acc(
    float* __restrict__ dst, const float* __restrict__ bias,
    int w, int lane, const float acc[3][4][4])
{
#pragma unroll
    for (int nt = 0; nt < 4; nt++) {
        const int col = w * 32 + nt * 8 + 2 * (lane & 3);
        const float2 cb = __ldg((const float2*)(bias + col));
#pragma unroll
        for (int mt = 0; mt < 3; mt++) {
            const int r0 = mt * 16 + (lane >> 2);
#pragma unroll
            for (int h2 = 0; h2 < 2; h2++) {
                const int r = r0 + 8 * h2;
                *(float2*)(dst + r * LDP + col) =
                    make_float2(acc[mt][nt][2 * h2] + cb.x, acc[mt][nt][2 * h2 + 1] + cb.y);
            }
        }
    }
}

__global__ void __launch_bounds__(256, 1)
mtb_kernel(const float* __restrict__ x,
           const float* __restrict__ bq, const float* __restrict__ bk,
           const float* __restrict__ bv,
           const float* __restrict__ memk, const float* __restrict__ memv,
           const float* __restrict__ bf,
           const float* __restrict__ gamma, const float* __restrict__ beta,
           const float* __restrict__ alpha_p,
           float* __restrict__ out)
{
    extern __shared__ float sm[];
    float* xs = sm;                        // x fp32 (kept for residual)
    float* qs = sm + 1 * MROWS * LDP;      // Q -> attn out (tf32 bits)
    float* ks = sm + 2 * MROWS * LDP;      // K
    float* vs = sm + 3 * MROWS * LDP;      // x tf32 (A operand) -> V -> pre-LN

    const int tid  = threadIdx.x;
    const int w    = tid >> 5;
    const int lane = tid & 31;
    const size_t gbase = (size_t)blockIdx.x * (MROWS * DD);

    // ---- stage x: fp32 into xs, tf32 bits into vs ----
    {
        const float4* xg = (const float4*)(x + gbase);
#pragma unroll
        for (int p = 0; p < 12; p++) {
            const int idx = p * 256 + tid;
            const int r = idx >> 6, cg = idx & 63;
            const float4 xv = xg[idx];
            *(float4*)(xs + r * LDP + cg * 4) = xv;
            float4 xt;
            xt.x = __uint_as_float(f2tf32(xv.x));
            xt.y = __uint_as_float(f2tf32(xv.y));
            xt.z = __uint_as_float(f2tf32(xv.z));
            xt.w = __uint_as_float(f2tf32(xv.w));
            *(float4*)(vs + r * LDP + cg * 4) = xt;
        }
    }
    __syncthreads();

    // ---- sweep 1: Q + K fused ----
    {
        float acc[2][3][4][4];
        const float2* Bp[2] = { &g_Wfrag[0][w][0][0][0], &g_Wfrag[1][w][0][0][0] };
        gemm_sweep<2>(vs, lane, Bp, acc);
        store_acc(qs, bq, w, lane, acc[0]);
        store_acc(ks, bk, w, lane, acc[1]);
    }
    // ---- sweep 2: V (A source is vs; sync before overwriting) ----
    {
        float acc[1][3][4][4];
        const float2* Bp[1] = { &g_Wfrag[2][w][0][0][0] };
        gemm_sweep<1>(vs, lane, Bp, acc);
        __syncthreads();                   // all A reads of vs complete
        store_acc(vs, bv, w, lane, acc[0]);
    }
    __syncthreads();

    // ---- attention: 32 units (tile,head); warp w -> units 4w..4w+3 ----
    // lane split: rep = lane>>3 owns t in {rep, rep+4, rep+8}; sub = lane&7 owns 4 dk.
    const float sl = 0.17677669529663687f * LOG2E;  // scale * log2(e)
    const float wl = 1.f / (1.f + __expf(-__ldg(alpha_p)));
    const float wt = 1.f - wl;
    const int rep = lane >> 3;
    const int sub = lane & 7;
    const unsigned gmask = 0xFFu << (8 * rep);

#pragma unroll
    for (int u = 0; u < 4; u++) {
        const int unit = w * 4 + u;
        const int tau = unit >> 3, h = unit & 7;
        const int rb = tau * TT;
        const int cb = h * 32 + sub * 4;

        float4 qv[3]; float4 ao[3]; float dn[3];
        float4 al[3]; float dml[3];
#pragma unroll
        for (int i = 0; i < 3; i++) {
            float4 q = *(const float4*)(qs + (rb + rep + 4 * i) * LDP + cb);
            qv[i] = make_float4(q.x * sl, q.y * sl, q.z * sl, q.w * sl);
            ao[i] = make_float4(0.f, 0.f, 0.f, 0.f);
            al[i] = make_float4(0.f, 0.f, 0.f, 0.f);
            dn[i] = 0.f; dml[i] = 0.f;
        }
        // causal temporal attention
#pragma unroll
        for (int s = 0; s < TT; s++) {
            const float4 kv = *(const float4*)(ks + (rb + s) * LDP + cb);
            const float4 vv = *(const float4*)(vs + (rb + s) * LDP + cb);
#pragma unroll
            for (int i = 0; i < 3; i++) {
                const int t = rep + 4 * i;
                if (t >= s) {              // uniform within the 8-lane group
                    float p = fmaf(qv[i].x, kv.x, fmaf(qv[i].y, kv.y,
                              fmaf(qv[i].z, kv.z, qv[i].w * kv.w)));
                    p = gsum8(p, gmask);
                    const float wg = ex2(p);
                    dn[i] += wg;
                    ao[i].x = fmaf(wg, vv.x, ao[i].x);
                    ao[i].y = fmaf(wg, vv.y, ao[i].y);
                    ao[i].z = fmaf(wg, vv.z, ao[i].z);
                    ao[i].w = fmaf(wg, vv.w, ao[i].w);
                }
            }
        }
        // memory-bank attention
#pragma unroll
        for (int m = 0; m < MMM; m++) {
            const float4 mk = __ldg((const float4*)(memk + (h * MMM + m) * 32 + sub * 4));
            const float4 mv = __ldg((const float4*)(memv + (h * MMM + m) * 32 + sub * 4));
#pragma unroll
            for (int i = 0; i < 3; i++) {
                float p = fmaf(qv[i].x, mk.x, fmaf(qv[i].y, mk.y,
                          fmaf(qv[i].z, mk.z, qv[i].w * mk.w)));
                p = gsum8(p, gmask);
                const float wg = ex2(p);
                dml[i] += wg;
                al[i].x = fmaf(wg, mv.x, al[i].x);
                al[i].y = fmaf(wg, mv.y, al[i].y);
                al[i].z = fmaf(wg, mv.z, al[i].z);
                al[i].w = fmaf(wg, mv.w, al[i].w);
            }
        }
        // gate + store as tf32 bits into qs (fc A operand)
#pragma unroll
        for (int i = 0; i < 3; i++) {
            const float id = wt / dn[i], il = wl / dml[i];
            float4 o;
            o.x = __uint_as_float(f2tf32(ao[i].x * id + al[i].x * il));
            o.y = __uint_as_float(f2tf32(ao[i].y * id + al[i].y * il));
            o.z = __uint_as_float(f2tf32(ao[i].z * id + al[i].z * il));
            o.w = __uint_as_float(f2tf32(ao[i].w * id + al[i].w * il));
            *(float4*)(qs + (rb + rep + 4 * i) * LDP + cb) = o;
        }
    }
    __syncthreads();

    // ---- sweep 3: fc ----
    {
        float acc[1][3][4][4];
        const float2* Bp[1] = { &g_Wfrag[3][w][0][0][0] };
        gemm_sweep<1>(qs, lane, Bp, acc);
        // bias + residual -> vs
#pragma unroll
        for (int nt = 0; nt < 4; nt++) {
            const int col = w * 32 + nt * 8 + 2 * (lane & 3);
            const float2 cbf = __ldg((const float2*)(bf + col));
#pragma unroll
            for (int mt = 0; mt < 3; mt++) {
                const int r0 = mt * 16 + (lane >> 2);
#pragma unroll
                for (int h2 = 0; h2 < 2; h2++) {
                    const int r = r0 + 8 * h2;
                    const float2 res = *(const float2*)(xs + r * LDP + col);
                    *(float2*)(vs + r * LDP + col) =
                        make_float2(acc[0][mt][nt][2 * h2] + cbf.x + res.x,
                                    acc[0][mt][nt][2 * h2 + 1] + cbf.y + res.y);
                }
            }
        }
    }
    __syncthreads();

    // ---- LayerNorm: warp per row ----
    for (int r = w * 6; r < w * 6 + 6; r++) {
        const float* row = vs + r * LDP;
        float s = 0.f, s2 = 0.f;
#pragma unroll
        for (int j = 0; j < 8; j++) {
            const float val = row[lane + 32 * j];
            s += val; s2 = fmaf(val, val, s2);
        }
        s = warp_sum(s); s2 = warp_sum(s2);
        const float mu = s * (1.f / 256.f);
        const float var = s2 * (1.f / 256.f) - mu * mu;
        const float inv = rsqrtf(var + 1e-5f);
        float* orow = out + gbase + (size_t)r * DD;
#pragma unroll
        for (int j = 0; j < 8; j++) {
            const int c = lane + 32 * j;
            orow[c] = (row[c] - mu) * inv * __ldg(gamma + c) + __ldg(beta + c);
        }
    }
}

extern "C" void kernel_launch(void* const* d_in, const int* in_sizes, int n_in,
                              void* d_out, int out_size)
{
    (void)in_sizes; (void)n_in; (void)out_size;
    const float* x     = (const float*)d_in[0];
    const float* Wq_w  = (const float*)d_in[1];
    const float* Wq_b  = (const float*)d_in[2];
    const float* Wk_w  = (const float*)d_in[3];
    const float* Wk_b  = (const float*)d_in[4];
    const float* Wv_w  = (const float*)d_in[5];
    const float* Wv_b  = (const float*)d_in[6];
    const float* mem_k = (const float*)d_in[7];
    const float* mem_v = (const float*)d_in[8];
    const float* fc_w  = (const float*)d_in[9];
    const float* fc_b  = (const float*)d_in[10];
    const float* gamma = (const float*)d_in[11];
    const float* beta  = (const float*)d_in[12];
    const float* alpha = (const float*)d_in[13];
    float* out = (float*)d_out;

    const int smemBytes = 4 * MROWS * LDP * sizeof(float);
    cudaFuncSetAttribute(mtb_kernel, cudaFuncAttributeMaxDynamicSharedMemorySize, smemBytes);

    prep_kernel<<<512, 256>>>(Wq_w, Wk_w, Wv_w, fc_w);
    mtb_kernel<<<16384 / GG, 256, smemBytes>>>(x, Wq_b, Wk_b, Wv_b, mem_k, mem_v,
                                               fc_b, gamma, beta, alpha, out);
}

// round 5
// speedup vs baseline: 6.4371x; 1.3831x over previous
#include <cuda_runtime.h>
#include <cuda_bf16.h>
#include <cstdint>

// MemoryTemporalBlock — bf16 m16n8k16 tensor-core version.
// One CTA per 4 (b,n) tiles (M=48 rows), 256 threads, ~220KB smem, 1 CTA/SM.
// GEMM A operands (x, attention-out) stored packed bf16; Q/K/V kept fp32 in
// smem for exact-ish attention. B operands pre-packed in bf16 fragment order.

#define TT 12
#define DD 256
#define GG 4
#define MROWS (GG * TT)
#define LDP 260        // fp32 buffer stride (floats)
#define LDPH 132       // bf16 buffer stride (uints = bf16x2)
#define MMM 8
#define LOG2E 1.4426950408889634f

// Wfrag[mat][wn(8)][kstep(16)][ntile(4)][lane(32)] as uint2 (4 bf16: k,k+1 / k+8,k+9)
__device__ uint2 g_Wfrag[4][8][16][4][32];

static __device__ __forceinline__ uint32_t pkbf(float lo, float hi) {
    __nv_bfloat162 h = __float22bfloat162_rn(make_float2(lo, hi));
    uint32_t r; memcpy(&r, &h, 4); return r;
}
static __device__ __forceinline__ float ex2(float x) {
    float r; asm("ex2.approx.f32 %0, %1;" : "=f"(r) : "f"(x)); return r;
}
static __device__ __forceinline__ void mma_bf16(float* c, const uint32_t* a,
                                                uint32_t b0, uint32_t b1) {
    asm("mma.sync.aligned.m16n8k16.row.col.f32.bf16.bf16.f32 "
        "{%0,%1,%2,%3}, {%4,%5,%6,%7}, {%8,%9}, {%0,%1,%2,%3};"
        : "+f"(c[0]), "+f"(c[1]), "+f"(c[2]), "+f"(c[3])
        : "r"(a[0]), "r"(a[1]), "r"(a[2]), "r"(a[3]), "r"(b0), "r"(b1));
}
static __device__ __forceinline__ float warp_sum(float v) {
#pragma unroll
    for (int o = 16; o; o >>= 1) v += __shfl_xor_sync(0xffffffffu, v, o);
    return v;
}
static __device__ __forceinline__ float gsum8(float v, unsigned m) {
    v += __shfl_xor_sync(m, v, 1);
    v += __shfl_xor_sync(m, v, 2);
    v += __shfl_xor_sync(m, v, 4);
    return v;
}

__global__ void prep_kernel(const float* __restrict__ wq, const float* __restrict__ wk,
                            const float* __restrict__ wv, const float* __restrict__ wf)
{
    // one thread per uint2 slot: 4*8*16*4*32 = 65536
    int i = blockIdx.x * blockDim.x + threadIdx.x;
    int lane = i & 31;
    int nt   = (i >> 5) & 3;
    int kk   = (i >> 7) & 15;
    int wn   = (i >> 11) & 7;
    int mat  = i >> 14;
    const float* W = (mat == 0) ? wq : (mat == 1) ? wk : (mat == 2) ? wv : wf;
    int e = wn * 32 + nt * 8 + (lane >> 2);
    int d = kk * 16 + (lane & 3) * 2;
    uint2 v;
    v.x = pkbf(__ldg(W + e * DD + d),     __ldg(W + e * DD + d + 1));
    v.y = pkbf(__ldg(W + e * DD + d + 8), __ldg(W + e * DD + d + 9));
    g_Wfrag[mat][wn][kk][nt][lane] = v;
}

// GEMM sweep over K=256 for NM weight matrices; A = packed bf16 smem [48][LDPH].
template<int NM>
static __device__ __forceinline__ void gemm_sweep(
    const uint32_t* __restrict__ As, int lane,
    const uint2* const* __restrict__ Bp,
    float acc[NM][3][4][4])
{
#pragma unroll
    for (int m = 0; m < NM; m++)
#pragma unroll
        for (int mt = 0; mt < 3; mt++)
#pragma unroll
            for (int nt = 0; nt < 4; nt++)
#pragma unroll
                for (int j = 0; j < 4; j++) acc[m][mt][nt][j] = 0.f;

    uint2 b0[NM][4], b1[NM][4];
#pragma unroll
    for (int m = 0; m < NM; m++)
#pragma unroll
        for (int nt = 0; nt < 4; nt++) {
            b0[m][nt] = __ldg(Bp[m] + nt * 32 + lane);
            b1[m][nt] = __ldg(Bp[m] + (4 + nt) * 32 + lane);
        }

    const int r0 = lane >> 2, c0 = lane & 3;
#pragma unroll 2
    for (int kk = 0; kk < 16; kk++) {
        uint32_t a[3][4];
#pragma unroll
        for (int mt = 0; mt < 3; mt++) {
            const uint32_t* p = As + (mt * 16 + r0) * LDPH + kk * 8 + c0;
            a[mt][0] = p[0];
            a[mt][1] = p[8 * LDPH];
            a[mt][2] = p[4];
            a[mt][3] = p[8 * LDPH + 4];
        }
        uint2 bc[NM][4];
#pragma unroll
        for (int m = 0; m < NM; m++)
#pragma unroll
            for (int nt = 0; nt < 4; nt++) { bc[m][nt] = b0[m][nt]; b0[m][nt] = b1[m][nt]; }
        if (kk < 14) {
#pragma unroll
            for (int m = 0; m < NM; m++)
#pragma unroll
                for (int nt = 0; nt < 4; nt++)
                    b1[m][nt] = __ldg(Bp[m] + ((kk + 2) * 4 + nt) * 32 + lane);
        }
#pragma unroll
        for (int m = 0; m < NM; m++)
#pragma unroll
            for (int nt = 0; nt < 4; nt++)
#pragma unroll
                for (int mt = 0; mt < 3; mt++)
                    mma_bf16(acc[m][mt][nt], a[mt], bc[m][nt].x, bc[m][nt].y);
    }
}

static __device__ __forceinline__ void store_acc(
    float* __restrict__ dst, const float* __restrict__ bias,
    int w, int lane, const float acc[3][4][4])
{
#pragma unroll
    for (int nt = 0; nt < 4; nt++) {
        const int col = w * 32 + nt * 8 + 2 * (lane & 3);
        const float2 cb = __ldg((const float2*)(bias + col));
#pragma unroll
        for (int mt = 0; mt < 3; mt++) {
            const int r0 = mt * 16 + (lane >> 2);
#pragma unroll
            for (int h2 = 0; h2 < 2; h2++) {
                const int r = r0 + 8 * h2;
                *(float2*)(dst + r * LDP + col) =
                    make_float2(acc[mt][nt][2 * h2] + cb.x, acc[mt][nt][2 * h2 + 1] + cb.y);
            }
        }
    }
}

__global__ void __launch_bounds__(256, 1)
mtb_kernel(const float* __restrict__ x,
           const float* __restrict__ bq, const float* __restrict__ bk,
           const float* __restrict__ bv,
           const float* __restrict__ memk, const float* __restrict__ memv,
           const float* __restrict__ bf,
           const float* __restrict__ gamma, const float* __restrict__ beta,
           const float* __restrict__ alpha_p,
           float* __restrict__ out)
{
    extern __shared__ float sm[];
    float* xs = sm;                                   // x fp32 (residual)
    float* qs = sm + 1 * MROWS * LDP;                 // Q fp32
    float* ks = sm + 2 * MROWS * LDP;                 // K fp32
    float* vs = sm + 3 * MROWS * LDP;                 // V fp32 -> pre-LN
    uint32_t* xb = (uint32_t*)(sm + 4 * MROWS * LDP); // bf16 A: x -> attn-out

    const int tid  = threadIdx.x;
    const int w    = tid >> 5;
    const int lane = tid & 31;
    const size_t gbase = (size_t)blockIdx.x * (MROWS * DD);

    // ---- stage x: fp32 into xs, packed bf16 into xb ----
    {
        const float4* xg = (const float4*)(x + gbase);
#pragma unroll
        for (int p = 0; p < 12; p++) {
            const int idx = p * 256 + tid;
            const int r = idx >> 6, cg = idx & 63;
            const float4 xv = xg[idx];
            *(float4*)(xs + r * LDP + cg * 4) = xv;
            xb[r * LDPH + cg * 2]     = pkbf(xv.x, xv.y);
            xb[r * LDPH + cg * 2 + 1] = pkbf(xv.z, xv.w);
        }
    }
    __syncthreads();

    // ---- sweep 1: Q + K fused ----
    {
        float acc[2][3][4][4];
        const uint2* Bp[2] = { &g_Wfrag[0][w][0][0][0], &g_Wfrag[1][w][0][0][0] };
        gemm_sweep<2>(xb, lane, Bp, acc);
        store_acc(qs, bq, w, lane, acc[0]);
        store_acc(ks, bk, w, lane, acc[1]);
    }
    // ---- sweep 2: V ----
    {
        float acc[1][3][4][4];
        const uint2* Bp[1] = { &g_Wfrag[2][w][0][0][0] };
        gemm_sweep<1>(xb, lane, Bp, acc);
        store_acc(vs, bv, w, lane, acc[0]);
    }
    __syncthreads();

    // ---- attention: 32 units (tile,head); warp w -> units 4w..4w+3 ----
    // lane split: rep = lane>>3 owns t in {rep, rep+4, rep+8}; sub = lane&7 owns 4 dk.
    const float sl = 0.17677669529663687f * LOG2E;
    const float wl = 1.f / (1.f + __expf(-__ldg(alpha_p)));
    const float wt = 1.f - wl;
    const int rep = lane >> 3;
    const int sub = lane & 7;
    const unsigned gmask = 0xFFu << (8 * rep);

#pragma unroll
    for (int u = 0; u < 4; u++) {
        const int unit = w * 4 + u;
        const int tau = unit >> 3, h = unit & 7;
        const int rb = tau * TT;
        const int cb = h * 32 + sub * 4;

        float4 qv[3]; float4 ao[3]; float dn[3];
        float4 al[3]; float dml[3];
#pragma unroll
        for (int i = 0; i < 3; i++) {
            float4 q = *(const float4*)(qs + (rb + rep + 4 * i) * LDP + cb);
            qv[i] = make_float4(q.x * sl, q.y * sl, q.z * sl, q.w * sl);
            ao[i] = make_float4(0.f, 0.f, 0.f, 0.f);
            al[i] = make_float4(0.f, 0.f, 0.f, 0.f);
            dn[i] = 0.f; dml[i] = 0.f;
        }
        // causal temporal attention
#pragma unroll
        for (int s = 0; s < TT; s++) {
            const float4 kv = *(const float4*)(ks + (rb + s) * LDP + cb);
            const float4 vv = *(const float4*)(vs + (rb + s) * LDP + cb);
#pragma unroll
            for (int i = 0; i < 3; i++) {
                const int t = rep + 4 * i;
                if (t >= s) {
                    float p = fmaf(qv[i].x, kv.x, fmaf(qv[i].y, kv.y,
                              fmaf(qv[i].z, kv.z, qv[i].w * kv.w)));
                    p = gsum8(p, gmask);
                    const float wg = ex2(p);
                    dn[i] += wg;
                    ao[i].x = fmaf(wg, vv.x, ao[i].x);
                    ao[i].y = fmaf(wg, vv.y, ao[i].y);
                    ao[i].z = fmaf(wg, vv.z, ao[i].z);
                    ao[i].w = fmaf(wg, vv.w, ao[i].w);
                }
            }
        }
        // memory-bank attention
#pragma unroll
        for (int m = 0; m < MMM; m++) {
            const float4 mk = __ldg((const float4*)(memk + (h * MMM + m) * 32 + sub * 4));
            const float4 mv = __ldg((const float4*)(memv + (h * MMM + m) * 32 + sub * 4));
#pragma unroll
            for (int i = 0; i < 3; i++) {
                float p = fmaf(qv[i].x, mk.x, fmaf(qv[i].y, mk.y,
                          fmaf(qv[i].z, mk.z, qv[i].w * mk.w)));
                p = gsum8(p, gmask);
                const float wg = ex2(p);
                dml[i] += wg;
                al[i].x = fmaf(wg, mv.x, al[i].x);
                al[i].y = fmaf(wg, mv.y, al[i].y);
                al[i].z = fmaf(wg, mv.z, al[i].z);
                al[i].w = fmaf(wg, mv.w, al[i].w);
            }
        }
        // gate + store packed bf16 into xb (fc A operand); xb reads finished pre-sync
#pragma unroll
        for (int i = 0; i < 3; i++) {
            const float id = wt / dn[i], il = wl / dml[i];
            const int r = rb + rep + 4 * i;
            xb[r * LDPH + h * 16 + sub * 2] =
                pkbf(ao[i].x * id + al[i].x * il, ao[i].y * id + al[i].y * il);
            xb[r * LDPH + h * 16 + sub * 2 + 1] =
                pkbf(ao[i].z * id + al[i].z * il, ao[i].w * id + al[i].w * il);
        }
    }
    __syncthreads();

    // ---- sweep 3: fc ----
    {
        float acc[1][3][4][4];
        const uint2* Bp[1] = { &g_Wfrag[3][w][0][0][0] };
        gemm_sweep<1>(xb, lane, Bp, acc);
        // bias + residual -> vs
#pragma unroll
        for (int nt = 0; nt < 4; nt++) {
            const int col = w * 32 + nt * 8 + 2 * (lane & 3);
            const float2 cbf = __ldg((const float2*)(bf + col));
#pragma unroll
            for (int mt = 0; mt < 3; mt++) {
                const int r0 = mt * 16 + (lane >> 2);
#pragma unroll
                for (int h2 = 0; h2 < 2; h2++) {
                    const int r = r0 + 8 * h2;
                    const float2 res = *(const float2*)(xs + r * LDP + col);
                    *(float2*)(vs + r * LDP + col) =
                        make_float2(acc[0][mt][nt][2 * h2] + cbf.x + res.x,
                                    acc[0][mt][nt][2 * h2 + 1] + cbf.y + res.y);
                }
            }
        }
    }
    __syncthreads();

    // ---- LayerNorm: warp per row ----
    for (int r = w * 6; r < w * 6 + 6; r++) {
        const float* row = vs + r * LDP;
        float s = 0.f, s2 = 0.f;
#pragma unroll
        for (int j = 0; j < 8; j++) {
            const float val = row[lane + 32 * j];
            s += val; s2 = fmaf(val, val, s2);
        }
        s = warp_sum(s); s2 = warp_sum(s2);
        const float mu = s * (1.f / 256.f);
        const float var = s2 * (1.f / 256.f) - mu * mu;
        const float inv = rsqrtf(var + 1e-5f);
        float* orow = out + gbase + (size_t)r * DD;
#pragma unroll
        for (int j = 0; j < 8; j++) {
            const int c = lane + 32 * j;
            orow[c] = (row[c] - mu) * inv * __ldg(gamma + c) + __ldg(beta + c);
        }
    }
}

extern "C" void kernel_launch(void* const* d_in, const int* in_sizes, int n_in,
                              void* d_out, int out_size)
{
    (void)in_sizes; (void)n_in; (void)out_size;
    const float* x     = (const float*)d_in[0];
    const float* Wq_w  = (const float*)d_in[1];
    const float* Wq_b  = (const float*)d_in[2];
    const float* Wk_w  = (const float*)d_in[3];
    const float* Wk_b  = (const float*)d_in[4];
    const float* Wv_w  = (const float*)d_in[5];
    const float* Wv_b  = (const float*)d_in[6];
    const float* mem_k = (const float*)d_in[7];
    const float* mem_v = (const float*)d_in[8];
    const float* fc_w  = (const float*)d_in[9];
    const float* fc_b  = (const float*)d_in[10];
    const float* gamma = (const float*)d_in[11];
    const float* beta  = (const float*)d_in[12];
    const float* alpha = (const float*)d_in[13];
    float* out = (float*)d_out;

    const int smemBytes = 4 * MROWS * LDP * sizeof(float)
                        + MROWS * LDPH * sizeof(uint32_t);   // 199680 + 25344 = 225024
    cudaFuncSetAttribute(mtb_kernel, cudaFuncAttributeMaxDynamicSharedMemorySize, smemBytes);

    prep_kernel<<<256, 256>>>(Wq_w, Wk_w, Wv_w, fc_w);
    mtb_kernel<<<16384 / GG, 256, smemBytes>>>(x, Wq_b, Wk_b, Wv_b, mem_k, mem_v,
                                               fc_b, gamma, beta, alpha, out);
}

// round 10
// speedup vs baseline: 7.4054x; 1.1504x over previous
#include <cuda_runtime.h>
#include <cuda_bf16.h>
#include <cstdint>

// MemoryTemporalBlock — bf16 m16n8k16, 2-CTA/SM occupancy version.
// One CTA per 2 (b,n) tiles (M=24 valid rows, padded to 32 for m16 tiles),
// 256 threads, ~110KB smem, regs<=128 -> 2 CTAs/SM.
// GEMM A rows 24..31 read garbage from the adjacent smem buffer (allowed:
// they only affect discarded output rows; stores are predicated off).

#define TT 12
#define DD 256
#define GG 2
#define MROWS (GG * TT)   // 24 valid rows
#define LDP 260           // fp32 buffer stride (floats)
#define LDPH 132          // bf16 buffer stride (uints = bf16x2)
#define MMM 8
#define LOG2E 1.4426950408889634f

// Wfrag[mat][wn(8)][kstep(16)][ntile(4)][lane(32)] as uint2 (4 bf16)
__device__ uint2 g_Wfrag[4][8][16][4][32];

static __device__ __forceinline__ uint32_t pkbf(float lo, float hi) {
    __nv_bfloat162 h = __float22bfloat162_rn(make_float2(lo, hi));
    uint32_t r; memcpy(&r, &h, 4); return r;
}
static __device__ __forceinline__ float ex2(float x) {
    float r; asm("ex2.approx.f32 %0, %1;" : "=f"(r) : "f"(x)); return r;
}
static __device__ __forceinline__ void mma_bf16(float* c, const uint32_t* a,
                                                uint32_t b0, uint32_t b1) {
    asm("mma.sync.aligned.m16n8k16.row.col.f32.bf16.bf16.f32 "
        "{%0,%1,%2,%3}, {%4,%5,%6,%7}, {%8,%9}, {%0,%1,%2,%3};"
        : "+f"(c[0]), "+f"(c[1]), "+f"(c[2]), "+f"(c[3])
        : "r"(a[0]), "r"(a[1]), "r"(a[2]), "r"(a[3]), "r"(b0), "r"(b1));
}
static __device__ __forceinline__ float warp_sum(float v) {
#pragma unroll
    for (int o = 16; o; o >>= 1) v += __shfl_xor_sync(0xffffffffu, v, o);
    return v;
}
static __device__ __forceinline__ float gsum8(float v, unsigned m) {
    v += __shfl_xor_sync(m, v, 1);
    v += __shfl_xor_sync(m, v, 2);
    v += __shfl_xor_sync(m, v, 4);
    return v;
}

__global__ void prep_kernel(const float* __restrict__ wq, const float* __restrict__ wk,
                            const float* __restrict__ wv, const float* __restrict__ wf)
{
    int i = blockIdx.x * blockDim.x + threadIdx.x;   // 65536 threads
    int lane = i & 31;
    int nt   = (i >> 5) & 3;
    int kk   = (i >> 7) & 15;
    int wn   = (i >> 11) & 7;
    int mat  = i >> 14;
    const float* W = (mat == 0) ? wq : (mat == 1) ? wk : (mat == 2) ? wv : wf;
    int e = wn * 32 + nt * 8 + (lane >> 2);
    int d = kk * 16 + (lane & 3) * 2;
    uint2 v;
    v.x = pkbf(__ldg(W + e * DD + d),     __ldg(W + e * DD + d + 1));
    v.y = pkbf(__ldg(W + e * DD + d + 8), __ldg(W + e * DD + d + 9));
    g_Wfrag[mat][wn][kk][nt][lane] = v;
}

// Single-matrix GEMM sweep over K=256; A = packed bf16 smem, m-tiles {0,1}.
static __device__ __forceinline__ void gemm_sweep(
    const uint32_t* __restrict__ As, int lane,
    const uint2* __restrict__ Bp,
    float acc[2][4][4])
{
#pragma unroll
    for (int mt = 0; mt < 2; mt++)
#pragma unroll
        for (int nt = 0; nt < 4; nt++)
#pragma unroll
            for (int j = 0; j < 4; j++) acc[mt][nt][j] = 0.f;

    uint2 b0[4], b1[4];
#pragma unroll
    for (int nt = 0; nt < 4; nt++) {
        b0[nt] = __ldg(Bp + nt * 32 + lane);
        b1[nt] = __ldg(Bp + (4 + nt) * 32 + lane);
    }

    const int r0 = lane >> 2, c0 = lane & 3;
#pragma unroll 2
    for (int kk = 0; kk < 16; kk++) {
        uint32_t a[2][4];
#pragma unroll
        for (int mt = 0; mt < 2; mt++) {
            const uint32_t* p = As + (mt * 16 + r0) * LDPH + kk * 8 + c0;
            a[mt][0] = p[0];
            a[mt][1] = p[8 * LDPH];
            a[mt][2] = p[4];
            a[mt][3] = p[8 * LDPH + 4];
        }
        uint2 bc[4];
#pragma unroll
        for (int nt = 0; nt < 4; nt++) { bc[nt] = b0[nt]; b0[nt] = b1[nt]; }
        if (kk < 14) {
#pragma unroll
            for (int nt = 0; nt < 4; nt++)
                b1[nt] = __ldg(Bp + ((kk + 2) * 4 + nt) * 32 + lane);
        }
#pragma unroll
        for (int nt = 0; nt < 4; nt++)
#pragma unroll
            for (int mt = 0; mt < 2; mt++)
                mma_bf16(acc[mt][nt], a[mt], bc[nt].x, bc[nt].y);
    }
}

static __device__ __forceinline__ void store_acc(
    float* __restrict__ dst, const float* __restrict__ bias,
    int w, int lane, const float acc[2][4][4])
{
#pragma unroll
    for (int nt = 0; nt < 4; nt++) {
        const int col = w * 32 + nt * 8 + 2 * (lane & 3);
        const float2 cb = __ldg((const float2*)(bias + col));
#pragma unroll
        for (int mt = 0; mt < 2; mt++) {
            const int r0 = mt * 16 + (lane >> 2);
#pragma unroll
            for (int h2 = 0; h2 < 2; h2++) {
                if (mt == 1 && h2 == 1) continue;   // rows 24..31 discarded
                const int r = r0 + 8 * h2;
                *(float2*)(dst + r * LDP + col) =
                    make_float2(acc[mt][nt][2 * h2] + cb.x, acc[mt][nt][2 * h2 + 1] + cb.y);
            }
        }
    }
}

__global__ void __launch_bounds__(256, 2)
mtb_kernel(const float* __restrict__ x,
           const float* __restrict__ bq, const float* __restrict__ bk,
           const float* __restrict__ bv,
           const float* __restrict__ memk, const float* __restrict__ memv,
           const float* __restrict__ bf,
           const float* __restrict__ gamma, const float* __restrict__ beta,
           const float* __restrict__ alpha_p,
           float* __restrict__ out)
{
    extern __shared__ float sm[];
    float*    xs = sm;                                    // x fp32 [24][260]
    uint32_t* xb = (uint32_t*)(sm + MROWS * LDP);         // bf16 A [24][132] (+overrun into qs)
    float*    qs = sm + MROWS * LDP + MROWS * LDPH;       // Q fp32
    float*    ks = qs + MROWS * LDP;                      // K fp32
    float*    vs = ks + MROWS * LDP;                      // V fp32 -> pre-LN

    const int tid  = threadIdx.x;
    const int w    = tid >> 5;
    const int lane = tid & 31;
    const size_t gbase = (size_t)blockIdx.x * (MROWS * DD);

    // ---- stage x: fp32 into xs, packed bf16 into xb ----
    {
        const float4* xg = (const float4*)(x + gbase);
#pragma unroll
        for (int p = 0; p < 6; p++) {
            const int idx = p * 256 + tid;
            const int r = idx >> 6, cg = idx & 63;
            const float4 xv = xg[idx];
            *(float4*)(xs + r * LDP + cg * 4) = xv;
            xb[r * LDPH + cg * 2]     = pkbf(xv.x, xv.y);
            xb[r * LDPH + cg * 2 + 1] = pkbf(xv.z, xv.w);
        }
    }
    __syncthreads();

    // ---- sweeps: Q, K, V (separate: keeps regs < 128) ----
    {
        float acc[2][4][4];
        gemm_sweep(xb, lane, &g_Wfrag[0][w][0][0][0], acc);
        store_acc(qs, bq, w, lane, acc);
        gemm_sweep(xb, lane, &g_Wfrag[1][w][0][0][0], acc);
        store_acc(ks, bk, w, lane, acc);
        gemm_sweep(xb, lane, &g_Wfrag[2][w][0][0][0], acc);
        store_acc(vs, bv, w, lane, acc);
    }
    __syncthreads();

    // ---- attention: 16 units (tile,head); warp w -> units 2w, 2w+1 ----
    const float sl = 0.17677669529663687f * LOG2E;
    const float wl = 1.f / (1.f + __expf(-__ldg(alpha_p)));
    const float wt = 1.f - wl;
    const int rep = lane >> 3;
    const int sub = lane & 7;
    const unsigned gmask = 0xFFu << (8 * rep);

#pragma unroll
    for (int u = 0; u < 2; u++) {
        const int unit = w * 2 + u;
        const int tau = unit >> 3, h = unit & 7;
        const int rb = tau * TT;
        const int cb = h * 32 + sub * 4;

        float4 qv[3]; float4 ao[3]; float dn[3];
        float4 al[3]; float dml[3];
#pragma unroll
        for (int i = 0; i < 3; i++) {
            float4 q = *(const float4*)(qs + (rb + rep + 4 * i) * LDP + cb);
            qv[i] = make_float4(q.x * sl, q.y * sl, q.z * sl, q.w * sl);
            ao[i] = make_float4(0.f, 0.f, 0.f, 0.f);
            al[i] = make_float4(0.f, 0.f, 0.f, 0.f);
            dn[i] = 0.f; dml[i] = 0.f;
        }
#pragma unroll
        for (int s = 0; s < TT; s++) {
            const float4 kv = *(const float4*)(ks + (rb + s) * LDP + cb);
            const float4 vv = *(const float4*)(vs + (rb + s) * LDP + cb);
#pragma unroll
            for (int i = 0; i < 3; i++) {
                const int t = rep + 4 * i;
                if (t >= s) {
                    float p = fmaf(qv[i].x, kv.x, fmaf(qv[i].y, kv.y,
                              fmaf(qv[i].z, kv.z, qv[i].w * kv.w)));
                    p = gsum8(p, gmask);
                    const float wg = ex2(p);
                    dn[i] += wg;
                    ao[i].x = fmaf(wg, vv.x, ao[i].x);
                    ao[i].y = fmaf(wg, vv.y, ao[i].y);
                    ao[i].z = fmaf(wg, vv.z, ao[i].z);
                    ao[i].w = fmaf(wg, vv.w, ao[i].w);
                }
            }
        }
#pragma unroll
        for (int m = 0; m < MMM; m++) {
            const float4 mk = __ldg((const float4*)(memk + (h * MMM + m) * 32 + sub * 4));
            const float4 mv = __ldg((const float4*)(memv + (h * MMM + m) * 32 + sub * 4));
#pragma unroll
            for (int i = 0; i < 3; i++) {
                float p = fmaf(qv[i].x, mk.x, fmaf(qv[i].y, mk.y,
                          fmaf(qv[i].z, mk.z, qv[i].w * mk.w)));
                p = gsum8(p, gmask);
                const float wg = ex2(p);
                dml[i] += wg;
                al[i].x = fmaf(wg, mv.x, al[i].x);
                al[i].y = fmaf(wg, mv.y, al[i].y);
                al[i].z = fmaf(wg, mv.z, al[i].z);
                al[i].w = fmaf(wg, mv.w, al[i].w);
            }
        }
#pragma unroll
        for (int i = 0; i < 3; i++) {
            const float id = wt / dn[i], il = wl / dml[i];
            const int r = rb + rep + 4 * i;
            xb[r * LDPH + h * 16 + sub * 2] =
                pkbf(ao[i].x * id + al[i].x * il, ao[i].y * id + al[i].y * il);
            xb[r * LDPH + h * 16 + sub * 2 + 1] =
                pkbf(ao[i].z * id + al[i].z * il, ao[i].w * id + al[i].w * il);
        }
    }
    __syncthreads();

    // ---- sweep: fc + bias + residual -> vs ----
    {
        float acc[2][4][4];
        gemm_sweep(xb, lane, &g_Wfrag[3][w][0][0][0], acc);
#pragma unroll
        for (int nt = 0; nt < 4; nt++) {
            const int col = w * 32 + nt * 8 + 2 * (lane & 3);
            const float2 cbf = __ldg((const float2*)(bf + col));
#pragma unroll
            for (int mt = 0; mt < 2; mt++) {
                const int r0 = mt * 16 + (lane >> 2);
#pragma unroll
                for (int h2 = 0; h2 < 2; h2++) {
                    if (mt == 1 && h2 == 1) continue;
                    const int r = r0 + 8 * h2;
                    const float2 res = *(const float2*)(xs + r * LDP + col);
                    *(float2*)(vs + r * LDP + col) =
                        make_float2(acc[mt][nt][2 * h2] + cbf.x + res.x,
                                    acc[mt][nt][2 * h2 + 1] + cbf.y + res.y);
                }
            }
        }
    }
    __syncthreads();

    // ---- LayerNorm: 3 rows per warp ----
    for (int r = w * 3; r < w * 3 + 3; r++) {
        const float* row = vs + r * LDP;
        float s = 0.f, s2 = 0.f;
#pragma unroll
        for (int j = 0; j < 8; j++) {
            const float val = row[lane + 32 * j];
            s += val; s2 = fmaf(val, val, s2);
        }
        s = warp_sum(s); s2 = warp_sum(s2);
        const float mu = s * (1.f / 256.f);
        const float var = s2 * (1.f / 256.f) - mu * mu;
        const float inv = rsqrtf(var + 1e-5f);
        float* orow = out + gbase + (size_t)r * DD;
#pragma unroll
        for (int j = 0; j < 8; j++) {
            const int c = lane + 32 * j;
            orow[c] = (row[c] - mu) * inv * __ldg(gamma + c) + __ldg(beta + c);
        }
    }
}

extern "C" void kernel_launch(void* const* d_in, const int* in_sizes, int n_in,
                              void* d_out, int out_size)
{
    (void)in_sizes; (void)n_in; (void)out_size;
    const float* x     = (const float*)d_in[0];
    const float* Wq_w  = (const float*)d_in[1];
    const float* Wq_b  = (const float*)d_in[2];
    const float* Wk_w  = (const float*)d_in[3];
    const float* Wk_b  = (const float*)d_in[4];
    const float* Wv_w  = (const float*)d_in[5];
    const float* Wv_b  = (const float*)d_in[6];
    const float* mem_k = (const float*)d_in[7];
    const float* mem_v = (const float*)d_in[8];
    const float* fc_w  = (const float*)d_in[9];
    const float* fc_b  = (const float*)d_in[10];
    const float* gamma = (const float*)d_in[11];
    const float* beta  = (const float*)d_in[12];
    const float* alpha = (const float*)d_in[13];
    float* out = (float*)d_out;

    // 4 fp32 buffers (24x260) + 1 bf16 buffer (24x132): 99840 + 12672 = 112512 B
    const int smemBytes = 4 * MROWS * LDP * (int)sizeof(float)
                        + MROWS * LDPH * (int)sizeof(uint32_t);
    cudaFuncSetAttribute(mtb_kernel, cudaFuncAttributeMaxDynamicSharedMemorySize, smemBytes);

    prep_kernel<<<256, 256>>>(Wq_w, Wk_w, Wv_w, fc_w);
    mtb_kernel<<<16384 / GG, 256, smemBytes>>>(x, Wq_b, Wk_b, Wv_b, mem_k, mem_v,
                                               fc_b, gamma, beta, alpha, out);
}